// round 2
// baseline (speedup 1.0000x reference)
#include <cuda_runtime.h>

// Problem constants (fixed by the dataset)
#define B_   4096
#define T_   128
#define H_   256
#define R_   16              // rows per CTA
#define NCTA (B_ / R_)       // 256

// ---------------------------------------------------------------------------
// Device scratch (no dynamic allocation allowed)
// ---------------------------------------------------------------------------
__device__ float4 g_packWhh[256 * 256];  // [k][j] -> (Whh_i, Whh_f, Whh_g, Whh_o)[j][k]
__device__ float4 g_packWih[3 * 256];    // [e][j]
__device__ float4 g_packBias[256];       // [j]    -> bih+bhh per gate
__device__ float  g_W2T[256 * 512];      // [k][j]
__device__ float  g_Wo1T[256 * 128];     // [k][j2]
__device__ float  g_W1T[7 * 256];        // [k][j]

// ---------------------------------------------------------------------------
// Prep kernel: transpose / gate-pack weights for coalesced LDG.128 streaming
// ---------------------------------------------------------------------------
__global__ void prep_kernel(const float* __restrict__ W1,
                            const float* __restrict__ W2,
                            const float* __restrict__ Wih,
                            const float* __restrict__ Whh,
                            const float* __restrict__ bih,
                            const float* __restrict__ bhh,
                            const float* __restrict__ Wo1)
{
    int k = blockIdx.x;    // 0..255
    int j = threadIdx.x;   // 0..255

    g_packWhh[k * 256 + j] = make_float4(Whh[(0   + j) * 256 + k],
                                         Whh[(256 + j) * 256 + k],
                                         Whh[(512 + j) * 256 + k],
                                         Whh[(768 + j) * 256 + k]);
    g_W2T[k * 512 + j]       = W2[(0   + j) * 256 + k];
    g_W2T[k * 512 + 256 + j] = W2[(256 + j) * 256 + k];
    if (j < 128) g_Wo1T[k * 128 + j] = Wo1[j * 256 + k];
    if (k < 7)   g_W1T[k * 256 + j] = W1[j * 7 + k];
    if (k < 3)   g_packWih[k * 256 + j] = make_float4(Wih[(0   + j) * 3 + k],
                                                      Wih[(256 + j) * 3 + k],
                                                      Wih[(512 + j) * 3 + k],
                                                      Wih[(768 + j) * 3 + k]);
    if (k == 0)  g_packBias[j] = make_float4(bih[0   + j] + bhh[0   + j],
                                             bih[256 + j] + bhh[256 + j],
                                             bih[512 + j] + bhh[512 + j],
                                             bih[768 + j] + bhh[768 + j]);
}

// ---------------------------------------------------------------------------
// Packed f32x2 helpers (sm_100+): doubles fp32 FMA throughput per issue
// ---------------------------------------------------------------------------
typedef unsigned long long u64;

__device__ __forceinline__ u64 fma2(u64 a, u64 b, u64 c) {
    u64 d;
    asm("fma.rn.f32x2 %0, %1, %2, %3;" : "=l"(d) : "l"(a), "l"(b), "l"(c));
    return d;
}
__device__ __forceinline__ u64 dup2(float x) {
    u64 d; unsigned xi = __float_as_uint(x);
    asm("mov.b64 %0, {%1, %2};" : "=l"(d) : "r"(xi), "r"(xi));
    return d;
}
__device__ __forceinline__ u64 pk(float lo, float hi) {
    u64 d;
    asm("mov.b64 %0, {%1, %2};" : "=l"(d)
        : "r"(__float_as_uint(lo)), "r"(__float_as_uint(hi)));
    return d;
}
__device__ __forceinline__ float2 unpk(u64 a) {
    unsigned lo, hi;
    asm("mov.b64 {%0, %1}, %2;" : "=r"(lo), "=r"(hi) : "l"(a));
    return make_float2(__uint_as_float(lo), __uint_as_float(hi));
}

__device__ __forceinline__ float sigmoidf_(float x) {
    return __fdividef(1.f, 1.f + __expf(-x));
}

// ---------------------------------------------------------------------------
// Main persistent kernel: one CTA handles 16 batch rows end-to-end.
// Thread t owns hidden unit j=t (all 4 gates), rows packed as f32x2 pairs.
// ---------------------------------------------------------------------------
__global__ void __launch_bounds__(256, 2)
lstm_kernel(const float* __restrict__ meta,
            const float* __restrict__ b1,
            const float* __restrict__ b2,
            const float* __restrict__ bo1,
            const float* __restrict__ Wo2,
            const float* __restrict__ bo2,
            float* __restrict__ out)
{
    __shared__ float h2[256][16];     // [k][row] current h (also enc1 staging)
    __shared__ float xs[3][16];       // [elem][row] current x (fed-back y)
    __shared__ float zb[16][128];     // decoder hidden
    __shared__ float metas[16][8];    // metadata rows (padded)
    __shared__ float wo2s[3 * 128];
    __shared__ float bo1s[128];
    __shared__ float bo2s[4];

    const int t    = threadIdx.x;
    const int row0 = blockIdx.x * R_;

    // ---- stage small tensors ----
    if (t < 128) {
        int r = t >> 3, e = t & 7;
        metas[r][e] = (e < 7) ? meta[(row0 + r) * 7 + e] : 0.f;
        bo1s[t] = bo1[t];
    }
    wo2s[t] = Wo2[t];
    if (t < 128) wo2s[256 + t] = Wo2[256 + t];
    if (t < 3)   bo2s[t] = bo2[t];
    if (t < 48) {
        int r = t / 3, o = t - 3 * (t / 3);
        xs[o][r] = meta[(row0 + r) * 7 + o];   // x0 = metadata[:, :3]
    }
    __syncthreads();

    // ---- encoder layer 1: enc1[r][t] = relu(meta[r] . W1[t] + b1[t]) ----
    {
        float a[16];
        float bb = b1[t];
        #pragma unroll
        for (int r = 0; r < 16; r++) a[r] = bb;
        #pragma unroll
        for (int k = 0; k < 7; k++) {
            float w = g_W1T[k * 256 + t];
            #pragma unroll
            for (int r = 0; r < 16; r++) a[r] += metas[r][k] * w;
        }
        #pragma unroll
        for (int r = 0; r < 16; r++) h2[t][r] = fmaxf(a[r], 0.f);
    }
    __syncthreads();

    // ---- encoder layer 2: h0 (col t), c0 (col 256+t) ----
    u64 c2[8];
    {
        u64 ha[8], ca[8];
        u64 bh = dup2(b2[t]), bc = dup2(b2[256 + t]);
        #pragma unroll
        for (int p = 0; p < 8; p++) { ha[p] = bh; ca[p] = bc; }
        #pragma unroll 2
        for (int k = 0; k < 256; k++) {
            u64 wh = dup2(g_W2T[k * 512 + t]);
            u64 wc = dup2(g_W2T[k * 512 + 256 + t]);
            #pragma unroll
            for (int p = 0; p < 8; p++) {
                u64 hp = *reinterpret_cast<const u64*>(&h2[k][2 * p]);
                ha[p] = fma2(hp, wh, ha[p]);
                ca[p] = fma2(hp, wc, ca[p]);
            }
        }
        __syncthreads();   // all threads done reading enc1 from h2
        #pragma unroll
        for (int p = 0; p < 8; p++) {
            float2 hv = unpk(ha[p]);
            float2 cv = unpk(ca[p]);
            h2[t][2 * p]     = fmaxf(hv.x, 0.f);
            h2[t][2 * p + 1] = fmaxf(hv.y, 0.f);
            c2[p] = pk(fmaxf(cv.x, 0.f), fmaxf(cv.y, 0.f));
        }
    }
    __syncthreads();

    const int j2   = t & 127;
    const int half = t >> 7;
    float* outp = out + (long)row0 * (T_ * 3);

    // =====================  LSTM scan  =====================
    for (int step = 0; step < T_; step++) {
        // ---- gate accumulation: gates[j] = bias + x.Wih + h.Whh ----
        u64 ai[8], af[8], ag[8], ao[8];
        {
            float4 bb = g_packBias[t];
            u64 bi = dup2(bb.x), bf = dup2(bb.y), bg = dup2(bb.z), bo = dup2(bb.w);
            #pragma unroll
            for (int p = 0; p < 8; p++) { ai[p] = bi; af[p] = bf; ag[p] = bg; ao[p] = bo; }
            #pragma unroll
            for (int e = 0; e < 3; e++) {
                float4 we = g_packWih[e * 256 + t];
                u64 wx = dup2(we.x), wy = dup2(we.y), wz = dup2(we.z), ww = dup2(we.w);
                #pragma unroll
                for (int p = 0; p < 8; p++) {
                    u64 xp = *reinterpret_cast<const u64*>(&xs[e][2 * p]);
                    ai[p] = fma2(xp, wx, ai[p]);
                    af[p] = fma2(xp, wy, af[p]);
                    ag[p] = fma2(xp, wz, ag[p]);
                    ao[p] = fma2(xp, ww, ao[p]);
                }
            }
        }
        {
            const float4* wp = g_packWhh + t;
            #pragma unroll 2
            for (int k = 0; k < 256; k++) {
                float4 w = wp[k * 256];
                u64 wx = dup2(w.x), wy = dup2(w.y), wz = dup2(w.z), ww = dup2(w.w);
                #pragma unroll
                for (int p = 0; p < 8; p++) {
                    u64 hp = *reinterpret_cast<const u64*>(&h2[k][2 * p]);
                    ai[p] = fma2(hp, wx, ai[p]);
                    af[p] = fma2(hp, wy, af[p]);
                    ag[p] = fma2(hp, wz, ag[p]);
                    ao[p] = fma2(hp, ww, ao[p]);
                }
            }
        }

        // ---- elementwise LSTM cell update ----
        float hn[16];
        #pragma unroll
        for (int p = 0; p < 8; p++) {
            float2 iv = unpk(ai[p]), fv = unpk(af[p]);
            float2 gv = unpk(ag[p]), ov = unpk(ao[p]);
            float2 cv = unpk(c2[p]);
            float c0n = sigmoidf_(fv.x) * cv.x + sigmoidf_(iv.x) * tanhf(gv.x);
            float c1n = sigmoidf_(fv.y) * cv.y + sigmoidf_(iv.y) * tanhf(gv.y);
            hn[2 * p]     = sigmoidf_(ov.x) * tanhf(c0n);
            hn[2 * p + 1] = sigmoidf_(ov.y) * tanhf(c1n);
            c2[p] = pk(c0n, c1n);
        }
        __syncthreads();   // everyone done reading old h
        #pragma unroll
        for (int r = 0; r < 16; r++) h2[t][r] = hn[r];
        __syncthreads();   // new h visible

        // ---- decoder layer 1: z = relu(h . Wo1^T + bo1) ----
        {
            u64 z[4];
            u64 bz = dup2(bo1s[j2]);
            #pragma unroll
            for (int p = 0; p < 4; p++) z[p] = bz;
            const float* wo = g_Wo1T + j2;
            #pragma unroll 2
            for (int k = 0; k < 256; k++) {
                u64 w = dup2(wo[k * 128]);
                #pragma unroll
                for (int p = 0; p < 4; p++) {
                    u64 hp = *reinterpret_cast<const u64*>(&h2[k][8 * half + 2 * p]);
                    z[p] = fma2(hp, w, z[p]);
                }
            }
            #pragma unroll
            for (int p = 0; p < 4; p++) {
                float2 zv = unpk(z[p]);
                zb[8 * half + 2 * p][j2]     = fmaxf(zv.x, 0.f);
                zb[8 * half + 2 * p + 1][j2] = fmaxf(zv.y, 0.f);
            }
        }
        __syncthreads();

        // ---- decoder layer 2: y = z . Wo2^T + bo2 ; feed back as next x ----
        if (t < 48) {
            int r = t / 3, o = t - 3 * (t / 3);
            float acc = bo2s[o];
            const float* zr = zb[r];
            const float* w2 = &wo2s[o * 128];
            #pragma unroll 8
            for (int j = 0; j < 128; j++) acc += zr[j] * w2[j];
            outp[r * (T_ * 3) + step * 3 + o] = acc;
            xs[o][r] = acc;
        }
        __syncthreads();   // xs / zb ready for next step
    }
}

// ---------------------------------------------------------------------------
// Launch
// ---------------------------------------------------------------------------
extern "C" void kernel_launch(void* const* d_in, const int* in_sizes, int n_in,
                              void* d_out, int out_size)
{
    const float* meta = (const float*)d_in[0];
    // d_in[1] = target_seq_len (int32, always 128)
    const float* W1   = (const float*)d_in[2];
    const float* b1   = (const float*)d_in[3];
    const float* W2   = (const float*)d_in[4];
    const float* b2   = (const float*)d_in[5];
    const float* Wih  = (const float*)d_in[6];
    const float* Whh  = (const float*)d_in[7];
    const float* bih  = (const float*)d_in[8];
    const float* bhh  = (const float*)d_in[9];
    const float* Wo1  = (const float*)d_in[10];
    const float* bo1  = (const float*)d_in[11];
    const float* Wo2  = (const float*)d_in[12];
    const float* bo2  = (const float*)d_in[13];
    float* out = (float*)d_out;

    prep_kernel<<<256, 256>>>(W1, W2, Wih, Whh, bih, bhh, Wo1);
    lstm_kernel<<<NCTA, 256>>>(meta, b1, b2, bo1, Wo2, bo2, out);
}

// round 4
// speedup vs baseline: 1.0917x; 1.0917x over previous
#include <cuda_runtime.h>

// Problem constants (fixed by the dataset)
#define B_   4096
#define T_   128
#define H_   256
#define R_   16              // rows per CTA
#define NCTA (B_ / R_)       // 256

// ---------------------------------------------------------------------------
// Device scratch (no dynamic allocation allowed)
// ---------------------------------------------------------------------------
__device__ float4 g_packWhh[256 * 256];  // [k][j] -> (Whh_i, Whh_f, Whh_g, Whh_o)[j][k]
__device__ float4 g_packWih[3 * 256];    // [e][j]
__device__ float4 g_packBias[256];       // [j]    -> bih+bhh per gate
__device__ float  g_W2T[256 * 512];      // [k][j]
__device__ float  g_Wo1T[256 * 128];     // [k][j2]
__device__ float  g_W1T[7 * 256];        // [k][j]

// ---------------------------------------------------------------------------
// Prep kernel: transpose / gate-pack weights for coalesced LDG.128 streaming
// ---------------------------------------------------------------------------
__global__ void prep_kernel(const float* __restrict__ W1,
                            const float* __restrict__ W2,
                            const float* __restrict__ Wih,
                            const float* __restrict__ Whh,
                            const float* __restrict__ bih,
                            const float* __restrict__ bhh,
                            const float* __restrict__ Wo1)
{
    int k = blockIdx.x;    // 0..255
    int j = threadIdx.x;   // 0..255

    g_packWhh[k * 256 + j] = make_float4(Whh[(0   + j) * 256 + k],
                                         Whh[(256 + j) * 256 + k],
                                         Whh[(512 + j) * 256 + k],
                                         Whh[(768 + j) * 256 + k]);
    g_W2T[k * 512 + j]       = W2[(0   + j) * 256 + k];
    g_W2T[k * 512 + 256 + j] = W2[(256 + j) * 256 + k];
    if (j < 128) g_Wo1T[k * 128 + j] = Wo1[j * 256 + k];
    if (k < 7)   g_W1T[k * 256 + j] = W1[j * 7 + k];
    if (k < 3)   g_packWih[k * 256 + j] = make_float4(Wih[(0   + j) * 3 + k],
                                                      Wih[(256 + j) * 3 + k],
                                                      Wih[(512 + j) * 3 + k],
                                                      Wih[(768 + j) * 3 + k]);
    if (k == 0)  g_packBias[j] = make_float4(bih[0   + j] + bhh[0   + j],
                                             bih[256 + j] + bhh[256 + j],
                                             bih[512 + j] + bhh[512 + j],
                                             bih[768 + j] + bhh[768 + j]);
}

// ---------------------------------------------------------------------------
// Packed f32x2 helpers (sm_100+): doubles fp32 FMA throughput per issue
// ---------------------------------------------------------------------------
typedef unsigned long long u64;

__device__ __forceinline__ u64 fma2(u64 a, u64 b, u64 c) {
    u64 d;
    asm("fma.rn.f32x2 %0, %1, %2, %3;" : "=l"(d) : "l"(a), "l"(b), "l"(c));
    return d;
}
__device__ __forceinline__ u64 dup2(float x) {
    u64 d; unsigned xi = __float_as_uint(x);
    asm("mov.b64 %0, {%1, %2};" : "=l"(d) : "r"(xi), "r"(xi));
    return d;
}
__device__ __forceinline__ u64 pk(float lo, float hi) {
    u64 d;
    asm("mov.b64 %0, {%1, %2};" : "=l"(d)
        : "r"(__float_as_uint(lo)), "r"(__float_as_uint(hi)));
    return d;
}
__device__ __forceinline__ float2 unpk(u64 a) {
    unsigned lo, hi;
    asm("mov.b64 {%0, %1}, %2;" : "=r"(lo), "=r"(hi) : "l"(a));
    return make_float2(__uint_as_float(lo), __uint_as_float(hi));
}

__device__ __forceinline__ float sigmoidf_(float x) {
    return __fdividef(1.f, 1.f + __expf(-x));
}

// ---------------------------------------------------------------------------
// Main persistent kernel: one CTA handles 16 batch rows end-to-end.
// Thread t owns hidden unit j=t (all 4 gates), rows packed as f32x2 pairs.
// ---------------------------------------------------------------------------
__global__ void __launch_bounds__(256, 2)
lstm_kernel(const float* __restrict__ meta,
            const float* __restrict__ b1,
            const float* __restrict__ b2,
            const float* __restrict__ bo1,
            const float* __restrict__ Wo2,
            const float* __restrict__ bo2,
            float* __restrict__ out)
{
    __shared__ float h2[256][16];     // [k][row] current h (also enc1 staging)
    __shared__ float xs[3][16];       // [elem][row] current x (fed-back y)
    __shared__ float zb[16][128];     // decoder hidden
    __shared__ float metas[16][8];    // metadata rows (padded)
    __shared__ float wo2s[3 * 128];
    __shared__ float bo1s[128];
    __shared__ float bo2s[4];

    const int t    = threadIdx.x;
    const int row0 = blockIdx.x * R_;

    // ---- stage small tensors ----
    if (t < 128) {
        int r = t >> 3, e = t & 7;
        metas[r][e] = (e < 7) ? meta[(row0 + r) * 7 + e] : 0.f;
        bo1s[t] = bo1[t];
    }
    wo2s[t] = Wo2[t];
    if (t < 128) wo2s[256 + t] = Wo2[256 + t];
    if (t < 3)   bo2s[t] = bo2[t];
    if (t < 48) {
        int r = t / 3, o = t - 3 * (t / 3);
        xs[o][r] = meta[(row0 + r) * 7 + o];   // x0 = metadata[:, :3]
    }
    __syncthreads();

    // ---- encoder layer 1: enc1[r][t] = relu(meta[r] . W1[t] + b1[t]) ----
    {
        float a[16];
        float bb = b1[t];
        #pragma unroll
        for (int r = 0; r < 16; r++) a[r] = bb;
        #pragma unroll
        for (int k = 0; k < 7; k++) {
            float w = g_W1T[k * 256 + t];
            #pragma unroll
            for (int r = 0; r < 16; r++) a[r] += metas[r][k] * w;
        }
        #pragma unroll
        for (int r = 0; r < 16; r++) h2[t][r] = fmaxf(a[r], 0.f);
    }
    __syncthreads();

    // ---- encoder layer 2: h0 (col t), c0 (col 256+t) ----
    u64 c2[8];
    {
        u64 ha[8], ca[8];
        u64 bh = dup2(b2[t]), bc = dup2(b2[256 + t]);
        #pragma unroll
        for (int p = 0; p < 8; p++) { ha[p] = bh; ca[p] = bc; }
        #pragma unroll 2
        for (int k = 0; k < 256; k++) {
            u64 wh = dup2(g_W2T[k * 512 + t]);
            u64 wc = dup2(g_W2T[k * 512 + 256 + t]);
            #pragma unroll
            for (int p = 0; p < 8; p++) {
                u64 hp = *reinterpret_cast<const u64*>(&h2[k][2 * p]);
                ha[p] = fma2(hp, wh, ha[p]);
                ca[p] = fma2(hp, wc, ca[p]);
            }
        }
        __syncthreads();   // all threads done reading enc1 from h2
        #pragma unroll
        for (int p = 0; p < 8; p++) {
            float2 hv = unpk(ha[p]);
            float2 cv = unpk(ca[p]);
            h2[t][2 * p]     = fmaxf(hv.x, 0.f);
            h2[t][2 * p + 1] = fmaxf(hv.y, 0.f);
            c2[p] = pk(fmaxf(cv.x, 0.f), fmaxf(cv.y, 0.f));
        }
    }
    __syncthreads();

    const int j2   = t & 127;
    const int half = t >> 7;
    float* outp = out + (long)row0 * (T_ * 3);

    // =====================  LSTM scan  =====================
    for (int step = 0; step < T_; step++) {
        // ---- gate accumulation: gates[j] = bias + x.Wih + h.Whh ----
        u64 ai[8], af[8], ag[8], ao[8];
        {
            float4 bb = g_packBias[t];
            u64 bi = dup2(bb.x), bf = dup2(bb.y), bg = dup2(bb.z), bo = dup2(bb.w);
            #pragma unroll
            for (int p = 0; p < 8; p++) { ai[p] = bi; af[p] = bf; ag[p] = bg; ao[p] = bo; }
            #pragma unroll
            for (int e = 0; e < 3; e++) {
                float4 we = g_packWih[e * 256 + t];
                u64 wx = dup2(we.x), wy = dup2(we.y), wz = dup2(we.z), ww = dup2(we.w);
                #pragma unroll
                for (int p = 0; p < 8; p++) {
                    u64 xp = *reinterpret_cast<const u64*>(&xs[e][2 * p]);
                    ai[p] = fma2(xp, wx, ai[p]);
                    af[p] = fma2(xp, wy, af[p]);
                    ag[p] = fma2(xp, wz, ag[p]);
                    ao[p] = fma2(xp, ww, ao[p]);
                }
            }
        }
        {
            const float4* wp = g_packWhh + t;
            #pragma unroll 2
            for (int k = 0; k < 256; k++) {
                float4 w = wp[k * 256];
                u64 wx = dup2(w.x), wy = dup2(w.y), wz = dup2(w.z), ww = dup2(w.w);
                #pragma unroll
                for (int p = 0; p < 8; p++) {
                    u64 hp = *reinterpret_cast<const u64*>(&h2[k][2 * p]);
                    ai[p] = fma2(hp, wx, ai[p]);
                    af[p] = fma2(hp, wy, af[p]);
                    ag[p] = fma2(hp, wz, ag[p]);
                    ao[p] = fma2(hp, ww, ao[p]);
                }
            }
        }

        // ---- elementwise LSTM cell update ----
        float hn[16];
        #pragma unroll
        for (int p = 0; p < 8; p++) {
            float2 iv = unpk(ai[p]), fv = unpk(af[p]);
            float2 gv = unpk(ag[p]), ov = unpk(ao[p]);
            float2 cv = unpk(c2[p]);
            float c0n = sigmoidf_(fv.x) * cv.x + sigmoidf_(iv.x) * tanhf(gv.x);
            float c1n = sigmoidf_(fv.y) * cv.y + sigmoidf_(iv.y) * tanhf(gv.y);
            hn[2 * p]     = sigmoidf_(ov.x) * tanhf(c0n);
            hn[2 * p + 1] = sigmoidf_(ov.y) * tanhf(c1n);
            c2[p] = pk(c0n, c1n);
        }
        __syncthreads();   // everyone done reading old h
        #pragma unroll
        for (int r = 0; r < 16; r++) h2[t][r] = hn[r];
        __syncthreads();   // new h visible

        // ---- decoder layer 1: z = relu(h . Wo1^T + bo1) ----
        {
            u64 z[4];
            u64 bz = dup2(bo1s[j2]);
            #pragma unroll
            for (int p = 0; p < 4; p++) z[p] = bz;
            const float* wo = g_Wo1T + j2;
            #pragma unroll 2
            for (int k = 0; k < 256; k++) {
                u64 w = dup2(wo[k * 128]);
                #pragma unroll
                for (int p = 0; p < 4; p++) {
                    u64 hp = *reinterpret_cast<const u64*>(&h2[k][8 * half + 2 * p]);
                    z[p] = fma2(hp, w, z[p]);
                }
            }
            #pragma unroll
            for (int p = 0; p < 4; p++) {
                float2 zv = unpk(z[p]);
                zb[8 * half + 2 * p][j2]     = fmaxf(zv.x, 0.f);
                zb[8 * half + 2 * p + 1][j2] = fmaxf(zv.y, 0.f);
            }
        }
        __syncthreads();

        // ---- decoder layer 2: y = z . Wo2^T + bo2 ; feed back as next x ----
        if (t < 48) {
            int r = t / 3, o = t - 3 * (t / 3);
            float acc = bo2s[o];
            const float* zr = zb[r];
            const float* w2 = &wo2s[o * 128];
            #pragma unroll 8
            for (int j = 0; j < 128; j++) acc += zr[j] * w2[j];
            outp[r * (T_ * 3) + step * 3 + o] = acc;
            xs[o][r] = acc;
        }
        __syncthreads();   // xs / zb ready for next step
    }
}

// ---------------------------------------------------------------------------
// Launch
// ---------------------------------------------------------------------------
extern "C" void kernel_launch(void* const* d_in, const int* in_sizes, int n_in,
                              void* d_out, int out_size)
{
    const float* meta = (const float*)d_in[0];
    // d_in[1] = target_seq_len (int32, always 128)
    const float* W1   = (const float*)d_in[2];
    const float* b1   = (const float*)d_in[3];
    const float* W2   = (const float*)d_in[4];
    const float* b2   = (const float*)d_in[5];
    const float* Wih  = (const float*)d_in[6];
    const float* Whh  = (const float*)d_in[7];
    const float* bih  = (const float*)d_in[8];
    const float* bhh  = (const float*)d_in[9];
    const float* Wo1  = (const float*)d_in[10];
    const float* bo1  = (const float*)d_in[11];
    const float* Wo2  = (const float*)d_in[12];
    const float* bo2  = (const float*)d_in[13];
    float* out = (float*)d_out;

    prep_kernel<<<256, 256>>>(W1, W2, Wih, Whh, bih, bhh, Wo1);
    lstm_kernel<<<NCTA, 256>>>(meta, b1, b2, bo1, Wo2, bo2, out);
}